// round 3
// baseline (speedup 1.0000x reference)
#include <cuda_runtime.h>
#include <cstddef>

#define BATCH   256
#define IN_DIM  2048
#define OUT_DIM 2048
#define STEPS   40

#define QSCALE   8192.0f          // 2^13
#define QINV     (1.0f/8192.0f)
#define CBIAS    8421376.0f       // 2^23 + 32768
#define MARGIN   2.0e-3f

// Scratch (static __device__ arrays; no allocation anywhere)
__device__ unsigned d_wq32[IN_DIM * (OUT_DIM / 2)];   // int16 biased-uint16 wq[i][o], packed pairs
__device__ int      d_list[BATCH * IN_DIM];           // input indices sorted by spike step, per batch
__device__ int      d_off [BATCH * (STEPS + 1)];      // per-batch step offsets into d_list
__device__ int      d_flags[BATCH * OUT_DIM];         // flagged (b<<11 | o)
__device__ int      d_nflag;

// ---------------------------------------------------------------------------
// Kernel 1: transpose + quantize weight [OUT][IN] fp32 -> wq [IN][OUT] u16-biased
// ---------------------------------------------------------------------------
__global__ __launch_bounds__(256) void quant_transpose(const float* __restrict__ w)
{
    __shared__ float tile[64][33];      // [o_local][i_local]
    const int i0 = blockIdx.x * 32;
    const int o0 = blockIdx.y * 64;
    const int tx = threadIdx.x, ty = threadIdx.y;

    if (blockIdx.x == 0 && blockIdx.y == 0 && tx == 0 && ty == 0)
        d_nflag = 0;

#pragma unroll
    for (int jj = 0; jj < 64; jj += 8)
        tile[ty + jj][tx] = w[(size_t)(o0 + ty + jj) * IN_DIM + i0 + tx];
    __syncthreads();

#pragma unroll
    for (int ii = ty; ii < 32; ii += 8) {
        float a = tile[2 * tx][ii];
        float b = tile[2 * tx + 1][ii];
        int qa = __float2int_rn(a * QSCALE);
        int qb = __float2int_rn(b * QSCALE);
        qa = max(-32768, min(32767, qa));
        qb = max(-32768, min(32767, qb));
        unsigned ua = (unsigned)(qa + 32768) & 0xFFFFu;
        unsigned ub = (unsigned)(qb + 32768) & 0xFFFFu;
        d_wq32[(size_t)(i0 + ii) * (OUT_DIM / 2) + (o0 >> 1) + tx] = ua | (ub << 16);
    }
}

// ---------------------------------------------------------------------------
// Kernel 2: per-batch counting sort of input indices by spike step.
// ---------------------------------------------------------------------------
__global__ void bucket_kernel(const float* __restrict__ inp)
{
    __shared__ int cnt[STEPS];
    __shared__ int cur[STEPS];
    const int b   = blockIdx.x;
    const int tid = threadIdx.x;

    if (tid < STEPS) cnt[tid] = 0;
    __syncthreads();

    for (int i = tid; i < IN_DIM; i += blockDim.x) {
        int s = (int)(inp[(size_t)b * IN_DIM + i] * 2.0f + 0.5f);
        atomicAdd(&cnt[s], 1);
    }
    __syncthreads();

    if (tid == 0) {
        int acc = 0;
        for (int k = 0; k < STEPS; k++) {
            int c = cnt[k];
            d_off[b * (STEPS + 1) + k] = acc;
            cur[k] = acc;
            acc += c;
        }
        d_off[b * (STEPS + 1) + STEPS] = acc;
    }
    __syncthreads();

    for (int i = tid; i < IN_DIM; i += blockDim.x) {
        int s = (int)(inp[(size_t)b * IN_DIM + i] * 2.0f + 0.5f);
        int p = atomicAdd(&cur[s], 1);
        d_list[b * IN_DIM + p] = i;
    }
}

// ---------------------------------------------------------------------------
// Kernel 3: LIF dynamics on int16 weights (exact integer bucket sums in fp32).
// 4 outputs/thread via LDG.64; per-warp early exit; marginal outputs flagged.
// ---------------------------------------------------------------------------
__device__ __forceinline__ float u16lo(unsigned r) {
    return __uint_as_float(__byte_perm(r, 0x4B000000u, 0x7410)) - CBIAS;
}
__device__ __forceinline__ float u16hi(unsigned r) {
    return __uint_as_float(__byte_perm(r, 0x4B000000u, 0x7432)) - CBIAS;
}

__global__ __launch_bounds__(256) void snn16_kernel(float* __restrict__ out)
{
    const int bid = blockIdx.x;
    const int b   = bid >> 1;                               // batch
    const int oc4 = (bid & 1) * 256 + threadIdx.x;          // 4-col group 0..511
    const int o0  = oc4 * 4;

    const uint2* __restrict__ wr  = reinterpret_cast<const uint2*>(d_wq32) + oc4;
    const int*   __restrict__ lst = d_list + b * IN_DIM;
    const int*   __restrict__ off = d_off + b * (STEPS + 1);

    float V0 = 0.f, V1 = 0.f, V2 = 0.f, V3 = 0.f;
    float I0 = 0.f, I1 = 0.f, I2 = 0.f, I3 = 0.f;
    float f0 = 0.f, f1 = 0.f, f2 = 0.f, f3 = 0.f;

    int j = 0;
    for (int k = 0; k < STEPS; k++) {
        V0 += 0.025f * (I0 - V0);
        V1 += 0.025f * (I1 - V1);
        V2 += 0.025f * (I2 - V2);
        V3 += 0.025f * (I3 - V3);

        const int e = __ldg(off + k + 1);
        float G0 = 0.f, G1 = 0.f, G2 = 0.f, G3 = 0.f;
        for (; j + 3 < e; j += 4) {
            int i0 = __ldg(lst + j), i1 = __ldg(lst + j + 1);
            int i2 = __ldg(lst + j + 2), i3 = __ldg(lst + j + 3);
            uint2 r0 = __ldg(wr + (size_t)i0 * (OUT_DIM / 4));
            uint2 r1 = __ldg(wr + (size_t)i1 * (OUT_DIM / 4));
            uint2 r2 = __ldg(wr + (size_t)i2 * (OUT_DIM / 4));
            uint2 r3 = __ldg(wr + (size_t)i3 * (OUT_DIM / 4));
            G0 += u16lo(r0.x); G1 += u16hi(r0.x); G2 += u16lo(r0.y); G3 += u16hi(r0.y);
            G0 += u16lo(r1.x); G1 += u16hi(r1.x); G2 += u16lo(r1.y); G3 += u16hi(r1.y);
            G0 += u16lo(r2.x); G1 += u16hi(r2.x); G2 += u16lo(r2.y); G3 += u16hi(r2.y);
            G0 += u16lo(r3.x); G1 += u16hi(r3.x); G2 += u16lo(r3.y); G3 += u16hi(r3.y);
        }
        for (; j < e; j++) {
            int i0 = __ldg(lst + j);
            uint2 r0 = __ldg(wr + (size_t)i0 * (OUT_DIM / 4));
            G0 += u16lo(r0.x); G1 += u16hi(r0.x); G2 += u16lo(r0.y); G3 += u16hi(r0.y);
        }

        I0 = fmaf(G0, QINV, 0.9f * I0);
        I1 = fmaf(G1, QINV, 0.9f * I1);
        I2 = fmaf(G2, QINV, 0.9f * I2);
        I3 = fmaf(G3, QINV, 0.9f * I3);

        // threshold / reset / flag marginal
        if (f0 == 0.f) {
            if (fabsf(V0 - 1.0f) < MARGIN) { int p = atomicAdd(&d_nflag, 1); d_flags[p] = (b << 11) | (o0 + 0); }
            if (V0 > 1.0f) { f0 = (float)k; V0 = 0.f; }
        } else if (V0 > 1.0f) V0 = 0.f;
        if (f1 == 0.f) {
            if (fabsf(V1 - 1.0f) < MARGIN) { int p = atomicAdd(&d_nflag, 1); d_flags[p] = (b << 11) | (o0 + 1); }
            if (V1 > 1.0f) { f1 = (float)k; V1 = 0.f; }
        } else if (V1 > 1.0f) V1 = 0.f;
        if (f2 == 0.f) {
            if (fabsf(V2 - 1.0f) < MARGIN) { int p = atomicAdd(&d_nflag, 1); d_flags[p] = (b << 11) | (o0 + 2); }
            if (V2 > 1.0f) { f2 = (float)k; V2 = 0.f; }
        } else if (V2 > 1.0f) V2 = 0.f;
        if (f3 == 0.f) {
            if (fabsf(V3 - 1.0f) < MARGIN) { int p = atomicAdd(&d_nflag, 1); d_flags[p] = (b << 11) | (o0 + 3); }
            if (V3 > 1.0f) { f3 = (float)k; V3 = 0.f; }
        } else if (V3 > 1.0f) V3 = 0.f;

        bool mydone = (f0 != 0.f) && (f1 != 0.f) && (f2 != 0.f) && (f3 != 0.f);
        if (__all_sync(0xFFFFFFFFu, mydone))
            break;
    }

    float4 r;
    r.x = (f0 == 0.f) ? 20.0f : f0;
    r.y = (f1 == 0.f) ? 20.0f : f1;
    r.z = (f2 == 0.f) ? 20.0f : f2;
    r.w = (f3 == 0.f) ? 20.0f : f3;
    reinterpret_cast<float4*>(out)[((size_t)b * OUT_DIM + o0) >> 2] = r;
}

// ---------------------------------------------------------------------------
// Kernel 4: exact fp32 fixup for flagged (b,o). Warp per element; lanes split
// each step bucket and read the ORIGINAL row-major weight row.
// ---------------------------------------------------------------------------
__global__ __launch_bounds__(256) void fixup_kernel(const float* __restrict__ w,
                                                    float* __restrict__ out)
{
    const int n     = d_nflag;
    const int lane  = threadIdx.x & 31;
    const int gwarp = (blockIdx.x * blockDim.x + threadIdx.x) >> 5;
    const int nwarp = (gridDim.x * blockDim.x) >> 5;

    for (int e = gwarp; e < n; e += nwarp) {
        const int code = d_flags[e];
        const int b = code >> 11;
        const int o = code & (OUT_DIM - 1);
        const float* __restrict__ row = w + (size_t)o * IN_DIM;
        const int*   __restrict__ lst = d_list + b * IN_DIM;
        const int*   __restrict__ off = d_off + b * (STEPS + 1);

        float V = 0.f, I = 0.f, res = 20.f;
        for (int k = 0; k < STEPS; k++) {
            V += 0.025f * (I - V);
            const int s  = __ldg(off + k);
            const int e2 = __ldg(off + k + 1);
            float g = 0.f;
            for (int jj = s + lane; jj < e2; jj += 32)
                g += __ldg(row + __ldg(lst + jj));
#pragma unroll
            for (int m = 16; m; m >>= 1)
                g += __shfl_xor_sync(0xFFFFFFFFu, g, m);
            I = 0.9f * I + g;
            if (V > 1.0f) { res = (float)k; break; }
        }
        if (lane == 0)
            out[(size_t)b * OUT_DIM + o] = res;
    }
}

// ---------------------------------------------------------------------------
extern "C" void kernel_launch(void* const* d_in, const int* in_sizes, int n_in,
                              void* d_out, int out_size)
{
    const float* inp = (const float*)d_in[0];
    const float* w   = (const float*)d_in[1];
    if (in_sizes[0] == IN_DIM * OUT_DIM) {   // defensive: identify by size
        const float* t = inp; inp = w; w = t;
    }

    quant_transpose<<<dim3(IN_DIM / 32, OUT_DIM / 64), dim3(32, 8)>>>(w);
    bucket_kernel<<<BATCH, 256>>>(inp);
    snn16_kernel<<<BATCH * 2, 256>>>((float*)d_out);
    fixup_kernel<<<128, 256>>>(w, (float*)d_out);
}

// round 4
// speedup vs baseline: 1.0014x; 1.0014x over previous
#include <cuda_runtime.h>
#include <cstddef>

#define BATCH   256
#define IN_DIM  2048
#define OUT_DIM 2048
#define STEPS   40

#define QSCALE   8192.0f          // 2^13
#define QINV     (1.0f/8192.0f)
#define CBIAS    8421376.0f       // 2^23 + 32768
#define MARGIN   2.0e-3f

// Scratch (static __device__ arrays; no allocation anywhere)
__device__ unsigned d_wq32[IN_DIM * (OUT_DIM / 2)];   // int16 biased-uint16 wq[i][o], packed pairs
__device__ int      d_list[BATCH * IN_DIM];           // input indices sorted by spike step, per batch
__device__ int      d_off [BATCH * (STEPS + 1)];      // per-batch step offsets into d_list
__device__ int      d_flags[BATCH * OUT_DIM];         // flagged (b<<11 | o)
__device__ int      d_nflag;

// ---------------------------------------------------------------------------
// Kernel 1: transpose + quantize weight [OUT][IN] fp32 -> wq [IN][OUT] u16-biased
// ---------------------------------------------------------------------------
__global__ __launch_bounds__(256) void quant_transpose(const float* __restrict__ w)
{
    __shared__ float tile[64][33];      // [o_local][i_local]
    const int i0 = blockIdx.x * 32;
    const int o0 = blockIdx.y * 64;
    const int tx = threadIdx.x, ty = threadIdx.y;

    if (blockIdx.x == 0 && blockIdx.y == 0 && tx == 0 && ty == 0)
        d_nflag = 0;

#pragma unroll
    for (int jj = 0; jj < 64; jj += 8)
        tile[ty + jj][tx] = w[(size_t)(o0 + ty + jj) * IN_DIM + i0 + tx];
    __syncthreads();

#pragma unroll
    for (int ii = ty; ii < 32; ii += 8) {
        float a = tile[2 * tx][ii];
        float b = tile[2 * tx + 1][ii];
        int qa = __float2int_rn(a * QSCALE);
        int qb = __float2int_rn(b * QSCALE);
        qa = max(-32768, min(32767, qa));
        qb = max(-32768, min(32767, qb));
        unsigned ua = (unsigned)(qa + 32768) & 0xFFFFu;
        unsigned ub = (unsigned)(qb + 32768) & 0xFFFFu;
        d_wq32[(size_t)(i0 + ii) * (OUT_DIM / 2) + (o0 >> 1) + tx] = ua | (ub << 16);
    }
}

// ---------------------------------------------------------------------------
// Kernel 2: per-batch counting sort of input indices by spike step.
// ---------------------------------------------------------------------------
__global__ void bucket_kernel(const float* __restrict__ inp)
{
    __shared__ int cnt[STEPS];
    __shared__ int cur[STEPS];
    const int b   = blockIdx.x;
    const int tid = threadIdx.x;

    if (tid < STEPS) cnt[tid] = 0;
    __syncthreads();

    for (int i = tid; i < IN_DIM; i += blockDim.x) {
        int s = (int)(inp[(size_t)b * IN_DIM + i] * 2.0f + 0.5f);
        atomicAdd(&cnt[s], 1);
    }
    __syncthreads();

    if (tid == 0) {
        int acc = 0;
        for (int k = 0; k < STEPS; k++) {
            int c = cnt[k];
            d_off[b * (STEPS + 1) + k] = acc;
            cur[k] = acc;
            acc += c;
        }
        d_off[b * (STEPS + 1) + STEPS] = acc;
    }
    __syncthreads();

    for (int i = tid; i < IN_DIM; i += blockDim.x) {
        int s = (int)(inp[(size_t)b * IN_DIM + i] * 2.0f + 0.5f);
        int p = atomicAdd(&cur[s], 1);
        d_list[b * IN_DIM + p] = i;
    }
}

// ---------------------------------------------------------------------------
// Kernel 3: LIF dynamics on int16 weights (exact integer bucket sums in fp32).
// 4 outputs/thread via LDG.64; per-warp early exit; marginal outputs flagged.
// ---------------------------------------------------------------------------
__device__ __forceinline__ float u16lo(unsigned r) {
    return __uint_as_float(__byte_perm(r, 0x4B000000u, 0x7410)) - CBIAS;
}
__device__ __forceinline__ float u16hi(unsigned r) {
    return __uint_as_float(__byte_perm(r, 0x4B000000u, 0x7432)) - CBIAS;
}

__global__ __launch_bounds__(256) void snn16_kernel(float* __restrict__ out)
{
    const int bid = blockIdx.x;
    const int b   = bid >> 1;                               // batch
    const int oc4 = (bid & 1) * 256 + threadIdx.x;          // 4-col group 0..511
    const int o0  = oc4 * 4;

    const uint2* __restrict__ wr  = reinterpret_cast<const uint2*>(d_wq32) + oc4;
    const int*   __restrict__ lst = d_list + b * IN_DIM;
    const int*   __restrict__ off = d_off + b * (STEPS + 1);

    float V0 = 0.f, V1 = 0.f, V2 = 0.f, V3 = 0.f;
    float I0 = 0.f, I1 = 0.f, I2 = 0.f, I3 = 0.f;
    float f0 = 0.f, f1 = 0.f, f2 = 0.f, f3 = 0.f;

    int j = 0;
    for (int k = 0; k < STEPS; k++) {
        V0 += 0.025f * (I0 - V0);
        V1 += 0.025f * (I1 - V1);
        V2 += 0.025f * (I2 - V2);
        V3 += 0.025f * (I3 - V3);

        const int e = __ldg(off + k + 1);
        float G0 = 0.f, G1 = 0.f, G2 = 0.f, G3 = 0.f;
        for (; j + 3 < e; j += 4) {
            int i0 = __ldg(lst + j), i1 = __ldg(lst + j + 1);
            int i2 = __ldg(lst + j + 2), i3 = __ldg(lst + j + 3);
            uint2 r0 = __ldg(wr + (size_t)i0 * (OUT_DIM / 4));
            uint2 r1 = __ldg(wr + (size_t)i1 * (OUT_DIM / 4));
            uint2 r2 = __ldg(wr + (size_t)i2 * (OUT_DIM / 4));
            uint2 r3 = __ldg(wr + (size_t)i3 * (OUT_DIM / 4));
            G0 += u16lo(r0.x); G1 += u16hi(r0.x); G2 += u16lo(r0.y); G3 += u16hi(r0.y);
            G0 += u16lo(r1.x); G1 += u16hi(r1.x); G2 += u16lo(r1.y); G3 += u16hi(r1.y);
            G0 += u16lo(r2.x); G1 += u16hi(r2.x); G2 += u16lo(r2.y); G3 += u16hi(r2.y);
            G0 += u16lo(r3.x); G1 += u16hi(r3.x); G2 += u16lo(r3.y); G3 += u16hi(r3.y);
        }
        for (; j < e; j++) {
            int i0 = __ldg(lst + j);
            uint2 r0 = __ldg(wr + (size_t)i0 * (OUT_DIM / 4));
            G0 += u16lo(r0.x); G1 += u16hi(r0.x); G2 += u16lo(r0.y); G3 += u16hi(r0.y);
        }

        I0 = fmaf(G0, QINV, 0.9f * I0);
        I1 = fmaf(G1, QINV, 0.9f * I1);
        I2 = fmaf(G2, QINV, 0.9f * I2);
        I3 = fmaf(G3, QINV, 0.9f * I3);

        // threshold / reset / flag marginal
        if (f0 == 0.f) {
            if (fabsf(V0 - 1.0f) < MARGIN) { int p = atomicAdd(&d_nflag, 1); d_flags[p] = (b << 11) | (o0 + 0); }
            if (V0 > 1.0f) { f0 = (float)k; V0 = 0.f; }
        } else if (V0 > 1.0f) V0 = 0.f;
        if (f1 == 0.f) {
            if (fabsf(V1 - 1.0f) < MARGIN) { int p = atomicAdd(&d_nflag, 1); d_flags[p] = (b << 11) | (o0 + 1); }
            if (V1 > 1.0f) { f1 = (float)k; V1 = 0.f; }
        } else if (V1 > 1.0f) V1 = 0.f;
        if (f2 == 0.f) {
            if (fabsf(V2 - 1.0f) < MARGIN) { int p = atomicAdd(&d_nflag, 1); d_flags[p] = (b << 11) | (o0 + 2); }
            if (V2 > 1.0f) { f2 = (float)k; V2 = 0.f; }
        } else if (V2 > 1.0f) V2 = 0.f;
        if (f3 == 0.f) {
            if (fabsf(V3 - 1.0f) < MARGIN) { int p = atomicAdd(&d_nflag, 1); d_flags[p] = (b << 11) | (o0 + 3); }
            if (V3 > 1.0f) { f3 = (float)k; V3 = 0.f; }
        } else if (V3 > 1.0f) V3 = 0.f;

        bool mydone = (f0 != 0.f) && (f1 != 0.f) && (f2 != 0.f) && (f3 != 0.f);
        if (__all_sync(0xFFFFFFFFu, mydone))
            break;
    }

    float4 r;
    r.x = (f0 == 0.f) ? 20.0f : f0;
    r.y = (f1 == 0.f) ? 20.0f : f1;
    r.z = (f2 == 0.f) ? 20.0f : f2;
    r.w = (f3 == 0.f) ? 20.0f : f3;
    reinterpret_cast<float4*>(out)[((size_t)b * OUT_DIM + o0) >> 2] = r;
}

// ---------------------------------------------------------------------------
// Kernel 4: exact fp32 fixup for flagged (b,o). Warp per element; lanes split
// each step bucket and read the ORIGINAL row-major weight row.
// ---------------------------------------------------------------------------
__global__ __launch_bounds__(256) void fixup_kernel(const float* __restrict__ w,
                                                    float* __restrict__ out)
{
    const int n     = d_nflag;
    const int lane  = threadIdx.x & 31;
    const int gwarp = (blockIdx.x * blockDim.x + threadIdx.x) >> 5;
    const int nwarp = (gridDim.x * blockDim.x) >> 5;

    for (int e = gwarp; e < n; e += nwarp) {
        const int code = d_flags[e];
        const int b = code >> 11;
        const int o = code & (OUT_DIM - 1);
        const float* __restrict__ row = w + (size_t)o * IN_DIM;
        const int*   __restrict__ lst = d_list + b * IN_DIM;
        const int*   __restrict__ off = d_off + b * (STEPS + 1);

        float V = 0.f, I = 0.f, res = 20.f;
        for (int k = 0; k < STEPS; k++) {
            V += 0.025f * (I - V);
            const int s  = __ldg(off + k);
            const int e2 = __ldg(off + k + 1);
            float g = 0.f;
            for (int jj = s + lane; jj < e2; jj += 32)
                g += __ldg(row + __ldg(lst + jj));
#pragma unroll
            for (int m = 16; m; m >>= 1)
                g += __shfl_xor_sync(0xFFFFFFFFu, g, m);
            I = 0.9f * I + g;
            if (V > 1.0f) { res = (float)k; break; }
        }
        if (lane == 0)
            out[(size_t)b * OUT_DIM + o] = res;
    }
}

// ---------------------------------------------------------------------------
extern "C" void kernel_launch(void* const* d_in, const int* in_sizes, int n_in,
                              void* d_out, int out_size)
{
    const float* inp = (const float*)d_in[0];
    const float* w   = (const float*)d_in[1];
    if (in_sizes[0] == IN_DIM * OUT_DIM) {   // defensive: identify by size
        const float* t = inp; inp = w; w = t;
    }

    quant_transpose<<<dim3(IN_DIM / 32, OUT_DIM / 64), dim3(32, 8)>>>(w);
    bucket_kernel<<<BATCH, 256>>>(inp);
    snn16_kernel<<<BATCH * 2, 256>>>((float*)d_out);
    fixup_kernel<<<128, 256>>>(w, (float*)d_out);
}

// round 5
// speedup vs baseline: 1.0017x; 1.0003x over previous
#include <cuda_runtime.h>
#include <cstddef>

#define BATCH   256
#define IN_DIM  2048
#define OUT_DIM 2048
#define STEPS   40

#define QSCALE   8192.0f          // 2^13
#define QINV     (1.0f/8192.0f)
#define CBIAS    8421376.0f       // 2^23 + 32768
#define MARGIN   2.0e-3f

// Scratch (static __device__ arrays; no allocation anywhere)
__device__ unsigned d_wq32[IN_DIM * (OUT_DIM / 2)];   // int16 biased-uint16 wq[i][o], packed pairs
__device__ int      d_list[BATCH * IN_DIM];           // input indices sorted by spike step, per batch
__device__ int      d_off [BATCH * (STEPS + 1)];      // per-batch step offsets into d_list
__device__ int      d_flags[BATCH * OUT_DIM];         // flagged (b<<11 | o)
__device__ int      d_nflag;

// ---------------------------------------------------------------------------
// Kernel 1: transpose + quantize weight [OUT][IN] fp32 -> wq [IN][OUT] u16-biased
// ---------------------------------------------------------------------------
__global__ __launch_bounds__(256) void quant_transpose(const float* __restrict__ w)
{
    __shared__ float tile[64][33];      // [o_local][i_local]
    const int i0 = blockIdx.x * 32;
    const int o0 = blockIdx.y * 64;
    const int tx = threadIdx.x, ty = threadIdx.y;

    if (blockIdx.x == 0 && blockIdx.y == 0 && tx == 0 && ty == 0)
        d_nflag = 0;

#pragma unroll
    for (int jj = 0; jj < 64; jj += 8)
        tile[ty + jj][tx] = w[(size_t)(o0 + ty + jj) * IN_DIM + i0 + tx];
    __syncthreads();

#pragma unroll
    for (int ii = ty; ii < 32; ii += 8) {
        float a = tile[2 * tx][ii];
        float b = tile[2 * tx + 1][ii];
        int qa = __float2int_rn(a * QSCALE);
        int qb = __float2int_rn(b * QSCALE);
        qa = max(-32768, min(32767, qa));
        qb = max(-32768, min(32767, qb));
        unsigned ua = (unsigned)(qa + 32768) & 0xFFFFu;
        unsigned ub = (unsigned)(qb + 32768) & 0xFFFFu;
        d_wq32[(size_t)(i0 + ii) * (OUT_DIM / 2) + (o0 >> 1) + tx] = ua | (ub << 16);
    }
}

// ---------------------------------------------------------------------------
// Kernel 2: per-batch counting sort of input indices by spike step.
// ---------------------------------------------------------------------------
__global__ void bucket_kernel(const float* __restrict__ inp)
{
    __shared__ int cnt[STEPS];
    __shared__ int cur[STEPS];
    const int b   = blockIdx.x;
    const int tid = threadIdx.x;

    if (tid < STEPS) cnt[tid] = 0;
    __syncthreads();

    for (int i = tid; i < IN_DIM; i += blockDim.x) {
        int s = (int)(inp[(size_t)b * IN_DIM + i] * 2.0f + 0.5f);
        atomicAdd(&cnt[s], 1);
    }
    __syncthreads();

    if (tid == 0) {
        int acc = 0;
        for (int k = 0; k < STEPS; k++) {
            int c = cnt[k];
            d_off[b * (STEPS + 1) + k] = acc;
            cur[k] = acc;
            acc += c;
        }
        d_off[b * (STEPS + 1) + STEPS] = acc;
    }
    __syncthreads();

    for (int i = tid; i < IN_DIM; i += blockDim.x) {
        int s = (int)(inp[(size_t)b * IN_DIM + i] * 2.0f + 0.5f);
        int p = atomicAdd(&cur[s], 1);
        d_list[b * IN_DIM + p] = i;
    }
}

// ---------------------------------------------------------------------------
// Kernel 3: LIF dynamics on int16 weights (exact integer bucket sums in fp32).
// 4 outputs/thread via LDG.64; per-warp early exit; marginal outputs flagged.
// ---------------------------------------------------------------------------
__device__ __forceinline__ float u16lo(unsigned r) {
    return __uint_as_float(__byte_perm(r, 0x4B000000u, 0x7410)) - CBIAS;
}
__device__ __forceinline__ float u16hi(unsigned r) {
    return __uint_as_float(__byte_perm(r, 0x4B000000u, 0x7432)) - CBIAS;
}

__global__ __launch_bounds__(256) void snn16_kernel(float* __restrict__ out)
{
    const int bid = blockIdx.x;
    const int b   = bid >> 1;                               // batch
    const int oc4 = (bid & 1) * 256 + threadIdx.x;          // 4-col group 0..511
    const int o0  = oc4 * 4;

    const uint2* __restrict__ wr  = reinterpret_cast<const uint2*>(d_wq32) + oc4;
    const int*   __restrict__ lst = d_list + b * IN_DIM;
    const int*   __restrict__ off = d_off + b * (STEPS + 1);

    float V0 = 0.f, V1 = 0.f, V2 = 0.f, V3 = 0.f;
    float I0 = 0.f, I1 = 0.f, I2 = 0.f, I3 = 0.f;
    float f0 = 0.f, f1 = 0.f, f2 = 0.f, f3 = 0.f;

    int j = 0;
    for (int k = 0; k < STEPS; k++) {
        V0 += 0.025f * (I0 - V0);
        V1 += 0.025f * (I1 - V1);
        V2 += 0.025f * (I2 - V2);
        V3 += 0.025f * (I3 - V3);

        const int e = __ldg(off + k + 1);
        float G0 = 0.f, G1 = 0.f, G2 = 0.f, G3 = 0.f;
        for (; j + 3 < e; j += 4) {
            int i0 = __ldg(lst + j), i1 = __ldg(lst + j + 1);
            int i2 = __ldg(lst + j + 2), i3 = __ldg(lst + j + 3);
            uint2 r0 = __ldg(wr + (size_t)i0 * (OUT_DIM / 4));
            uint2 r1 = __ldg(wr + (size_t)i1 * (OUT_DIM / 4));
            uint2 r2 = __ldg(wr + (size_t)i2 * (OUT_DIM / 4));
            uint2 r3 = __ldg(wr + (size_t)i3 * (OUT_DIM / 4));
            G0 += u16lo(r0.x); G1 += u16hi(r0.x); G2 += u16lo(r0.y); G3 += u16hi(r0.y);
            G0 += u16lo(r1.x); G1 += u16hi(r1.x); G2 += u16lo(r1.y); G3 += u16hi(r1.y);
            G0 += u16lo(r2.x); G1 += u16hi(r2.x); G2 += u16lo(r2.y); G3 += u16hi(r2.y);
            G0 += u16lo(r3.x); G1 += u16hi(r3.x); G2 += u16lo(r3.y); G3 += u16hi(r3.y);
        }
        for (; j < e; j++) {
            int i0 = __ldg(lst + j);
            uint2 r0 = __ldg(wr + (size_t)i0 * (OUT_DIM / 4));
            G0 += u16lo(r0.x); G1 += u16hi(r0.x); G2 += u16lo(r0.y); G3 += u16hi(r0.y);
        }

        I0 = fmaf(G0, QINV, 0.9f * I0);
        I1 = fmaf(G1, QINV, 0.9f * I1);
        I2 = fmaf(G2, QINV, 0.9f * I2);
        I3 = fmaf(G3, QINV, 0.9f * I3);

        // threshold / reset / flag marginal
        if (f0 == 0.f) {
            if (fabsf(V0 - 1.0f) < MARGIN) { int p = atomicAdd(&d_nflag, 1); d_flags[p] = (b << 11) | (o0 + 0); }
            if (V0 > 1.0f) { f0 = (float)k; V0 = 0.f; }
        } else if (V0 > 1.0f) V0 = 0.f;
        if (f1 == 0.f) {
            if (fabsf(V1 - 1.0f) < MARGIN) { int p = atomicAdd(&d_nflag, 1); d_flags[p] = (b << 11) | (o0 + 1); }
            if (V1 > 1.0f) { f1 = (float)k; V1 = 0.f; }
        } else if (V1 > 1.0f) V1 = 0.f;
        if (f2 == 0.f) {
            if (fabsf(V2 - 1.0f) < MARGIN) { int p = atomicAdd(&d_nflag, 1); d_flags[p] = (b << 11) | (o0 + 2); }
            if (V2 > 1.0f) { f2 = (float)k; V2 = 0.f; }
        } else if (V2 > 1.0f) V2 = 0.f;
        if (f3 == 0.f) {
            if (fabsf(V3 - 1.0f) < MARGIN) { int p = atomicAdd(&d_nflag, 1); d_flags[p] = (b << 11) | (o0 + 3); }
            if (V3 > 1.0f) { f3 = (float)k; V3 = 0.f; }
        } else if (V3 > 1.0f) V3 = 0.f;

        bool mydone = (f0 != 0.f) && (f1 != 0.f) && (f2 != 0.f) && (f3 != 0.f);
        if (__all_sync(0xFFFFFFFFu, mydone))
            break;
    }

    float4 r;
    r.x = (f0 == 0.f) ? 20.0f : f0;
    r.y = (f1 == 0.f) ? 20.0f : f1;
    r.z = (f2 == 0.f) ? 20.0f : f2;
    r.w = (f3 == 0.f) ? 20.0f : f3;
    reinterpret_cast<float4*>(out)[((size_t)b * OUT_DIM + o0) >> 2] = r;
}

// ---------------------------------------------------------------------------
// Kernel 4: exact fp32 fixup for flagged (b,o). Warp per element; lanes split
// each step bucket and read the ORIGINAL row-major weight row.
// ---------------------------------------------------------------------------
__global__ __launch_bounds__(256) void fixup_kernel(const float* __restrict__ w,
                                                    float* __restrict__ out)
{
    const int n     = d_nflag;
    const int lane  = threadIdx.x & 31;
    const int gwarp = (blockIdx.x * blockDim.x + threadIdx.x) >> 5;
    const int nwarp = (gridDim.x * blockDim.x) >> 5;

    for (int e = gwarp; e < n; e += nwarp) {
        const int code = d_flags[e];
        const int b = code >> 11;
        const int o = code & (OUT_DIM - 1);
        const float* __restrict__ row = w + (size_t)o * IN_DIM;
        const int*   __restrict__ lst = d_list + b * IN_DIM;
        const int*   __restrict__ off = d_off + b * (STEPS + 1);

        float V = 0.f, I = 0.f, res = 20.f;
        for (int k = 0; k < STEPS; k++) {
            V += 0.025f * (I - V);
            const int s  = __ldg(off + k);
            const int e2 = __ldg(off + k + 1);
            float g = 0.f;
            for (int jj = s + lane; jj < e2; jj += 32)
                g += __ldg(row + __ldg(lst + jj));
#pragma unroll
            for (int m = 16; m; m >>= 1)
                g += __shfl_xor_sync(0xFFFFFFFFu, g, m);
            I = 0.9f * I + g;
            if (V > 1.0f) { res = (float)k; break; }
        }
        if (lane == 0)
            out[(size_t)b * OUT_DIM + o] = res;
    }
}

// ---------------------------------------------------------------------------
extern "C" void kernel_launch(void* const* d_in, const int* in_sizes, int n_in,
                              void* d_out, int out_size)
{
    const float* inp = (const float*)d_in[0];
    const float* w   = (const float*)d_in[1];
    if (in_sizes[0] == IN_DIM * OUT_DIM) {   // defensive: identify by size
        const float* t = inp; inp = w; w = t;
    }

    quant_transpose<<<dim3(IN_DIM / 32, OUT_DIM / 64), dim3(32, 8)>>>(w);
    bucket_kernel<<<BATCH, 256>>>(inp);
    snn16_kernel<<<BATCH * 2, 256>>>((float*)d_out);
    fixup_kernel<<<128, 256>>>(w, (float*)d_out);
}